// round 14
// baseline (speedup 1.0000x reference)
#include <cuda_runtime.h>
#include <cstdint>
#include <cstddef>

namespace {

constexpr int kB  = 4;
constexpr int kH  = 8;
constexpr int kL  = 2048;
constexpr int kR  = 8;
constexpr int kDV = 128;

constexpr int TM = 64;           // rows per CTA
constexpr int KT = 32;           // K-tile
constexpr int NT = 256;          // threads
constexpr int NTILES = kL / KT;  // 64
constexpr int NEP = NTILES / 2;  // 32 epochs, 2 tiles each

constexpr int PSTRIDE = 36;      // p row stride (u32): ldmatrix rows hit distinct 16B groups
constexpr int VSTRIDE = 136;     // v row stride (u32): B-frag conflict-free
constexpr float kLog2e = 1.44269504088896340736f;

constexpr int PBUFB  = TM * PSTRIDE * 4;   // 9216 B per p buffer
constexpr int VSLOTB = KT * VSTRIDE * 4;   // 17408 B per v slot

typedef unsigned long long ull;

__device__ __forceinline__ ull dup2(float x) {
    ull r; asm("mov.b64 %0, {%1,%1};" : "=l"(r) : "f"(x)); return r;
}
__device__ __forceinline__ void unpack2(ull v, float& lo, float& hi) {
    asm("mov.b64 {%0,%1}, %2;" : "=f"(lo), "=f"(hi) : "l"(v));
}
__device__ __forceinline__ ull fma2(ull a, ull b, ull c) {
    ull d; asm("fma.rn.f32x2 %0, %1, %2, %3;" : "=l"(d) : "l"(a), "l"(b), "l"(c));
    return d;
}
__device__ __forceinline__ uint32_t f2tf32(float x) {
    uint32_t r; asm("cvt.rna.tf32.f32 %0, %1;" : "=r"(r) : "f"(x)); return r;
}
__device__ __forceinline__ float ex2(float x) {
    float r; asm("ex2.approx.f32 %0, %1;" : "=f"(r) : "f"(x)); return r;
}
__device__ __forceinline__ void mma_tf32(float d[4], const uint32_t a[4],
                                         uint32_t b0, uint32_t b1) {
    asm volatile(
        "mma.sync.aligned.m16n8k8.row.col.f32.tf32.tf32.f32 "
        "{%0,%1,%2,%3}, {%4,%5,%6,%7}, {%8,%9}, {%0,%1,%2,%3};"
        : "+f"(d[0]), "+f"(d[1]), "+f"(d[2]), "+f"(d[3])
        : "r"(a[0]), "r"(a[1]), "r"(a[2]), "r"(a[3]), "r"(b0), "r"(b1));
}
__device__ __forceinline__ void ldmatrix_x4(uint32_t a[4], uint32_t addr) {
    asm volatile(
        "ldmatrix.sync.aligned.m8n8.x4.shared.b16 {%0,%1,%2,%3}, [%4];"
        : "=r"(a[0]), "=r"(a[1]), "=r"(a[2]), "=r"(a[3]) : "r"(addr));
}
__device__ __forceinline__ uint32_t smem_u32(const void* p) {
    uint32_t a;
    asm("{ .reg .u64 t; cvta.to.shared.u64 t, %1; cvt.u32.u64 %0, t; }"
        : "=r"(a) : "l"(p));
    return a;
}
__device__ __forceinline__ void cp16(uint32_t saddr, const void* g) {
    asm volatile("cp.async.ca.shared.global [%0], [%1], 16;"
                 :: "r"(saddr), "l"(g) : "memory");
}
__device__ __forceinline__ void cp_commit() {
    asm volatile("cp.async.commit_group;" ::: "memory");
}
__device__ __forceinline__ void cp_wait0() {
    asm volatile("cp.async.wait_group 0;" ::: "memory");
}

struct __align__(16) SmemLayout {
    uint32_t p[4][TM][PSTRIDE];    // 36.9 KB (tf32 E tiles, 4-slot ring)
    uint32_t v[4][KT][VSTRIDE];    // 69.6 KB (raw f32 v tiles, cp.async ring)
    float    a2t[4][kR][KT];       // 4 KB    (streamed a2 K-tiles, 4-slot ring)
    float    inv[TM];              // 256 B
};
// 108.3 KB -> 2 CTAs/SM

// MMA of one K-tile: A fragments via ldmatrix from p buffer, B via LDS from v slot.
__device__ __forceinline__ void mma_tile(float acc[2][4][4], uint32_t ab,
                                         const uint32_t* vt,
                                         int wn, int qid, int tig) {
    #pragma unroll
    for (int s = 0; s < 4; ++s) {
        uint32_t a[2][4];
        ldmatrix_x4(a[0], ab + (uint32_t)(s * 32));
        ldmatrix_x4(a[1], ab + (uint32_t)(16 * PSTRIDE * 4 + s * 32));
        #pragma unroll
        for (int nt = 0; nt < 4; ++nt) {
            const int n = 32 * wn + 8 * nt + qid;
            uint32_t b0 = vt[(size_t)(8 * s + tig) * VSTRIDE + n];
            uint32_t b1 = vt[(size_t)(8 * s + 4 + tig) * VSTRIDE + n];
            mma_tf32(acc[0][nt], a[0], b0, b1);
            mma_tf32(acc[1][nt], a[1], b0, b1);
        }
    }
}

__global__ void __launch_bounds__(NT, 2)
fra_kernel(const float* __restrict__ gv,
           const float* __restrict__ ga1,
           const float* __restrict__ ga2,
           const int*   __restrict__ gmask,
           float* __restrict__ gout,
           float* __restrict__ gattn)
{
    extern __shared__ char smem_raw[];
    SmemLayout& S = *reinterpret_cast<SmemLayout*>(smem_raw);

    const int h    = blockIdx.x;   // heads fastest: 8 heads share mask tile in L2
    const int tile = blockIdx.y;
    const int b    = blockIdx.z;
    const int bh   = b * kH + h;
    const int i0g  = tile * TM;
    const int t    = threadIdx.x;
    const int w    = t >> 5;
    const int l    = t & 31;

    const float* a2base = ga2 + (size_t)bh * kR * kL;
    const float* a1base = ga1 + ((size_t)bh * kL + i0g) * kR;
    const float* vbase  = gv  + (size_t)bh * kL * kDV;
    const int*   mbase  = gmask + ((size_t)b * kL + i0g) * kL;
    float* attnbase = gattn + ((size_t)bh * kL + i0g) * kL;
    float* outbase  = gout  + ((size_t)bh * kL + i0g) * kDV;

    // score mapping: rows 2*rp+i (i=0,1), cols cg*4 within K-tile
    const int rp = t >> 3;   // 0..31
    const int cg = t & 7;    // 0..7

    // a1 (pre-scaled by log2e for ex2) for this thread's 2 rows
    float a1r[2][kR];
    #pragma unroll
    for (int i = 0; i < 2; ++i) {
        const float4* src = (const float4*)(a1base + (size_t)(rp * 2 + i) * kR);
        float4 q0 = src[0], q1 = src[1];
        a1r[i][0] = q0.x * kLog2e; a1r[i][1] = q0.y * kLog2e;
        a1r[i][2] = q0.z * kLog2e; a1r[i][3] = q0.w * kLog2e;
        a1r[i][4] = q1.x * kLog2e; a1r[i][5] = q1.y * kLog2e;
        a1r[i][6] = q1.z * kLog2e; a1r[i][7] = q1.w * kLog2e;
    }

    // GEMM warp grid 2x4 (wm x wn); warp tile 32 rows x 32 cols
    const int wm  = w >> 2;
    const int wn  = w & 3;
    const int qid = l >> 2;
    const int tig = l & 3;

    // ldmatrix A lane address (within p buffer 0; other buffers by +slot*PBUFB)
    const int lrow = 32 * wm + ((l >> 3) & 1) * 8 + (l & 7);
    const int lcol = ((l >> 4) & 1) * 4;
    const uint32_t paddr0 = smem_u32(&S.p[0][lrow][lcol]);

    float acc[2][4][4];
    #pragma unroll
    for (int mt = 0; mt < 2; ++mt)
        #pragma unroll
        for (int nt = 0; nt < 4; ++nt)
            #pragma unroll
            for (int e = 0; e < 4; ++e) acc[mt][nt][e] = 0.f;

    float rs[2] = {0.f, 0.f};

    // ---- cp.async v addressing ----
    const uint32_t vs_base = smem_u32(&S.v[0][0][0]);
    uint32_t voff[4];
    #pragma unroll
    for (int k = 0; k < 4; ++k)
        voff[k] = (uint32_t)(((w + 8 * k) * VSTRIDE + 4 * l) * 4);
    const float* vg[4];
    #pragma unroll
    for (int k = 0; k < 4; ++k)
        vg[k] = vbase + (size_t)(w + 8 * k) * kDV + 4 * l;
    constexpr size_t VGT = (size_t)KT * kDV;

    // a2 staging: 1 float per thread per tile (all warps balanced)
    const int ac2 = t & 31;            // col within tile
    const float* a2row = a2base + (size_t)w * kL;   // w = a2 row 0..7

    const uint32_t vbaseS = smem_u32(&S.v[0][0][0]); (void)vbaseS;

    // =============== per-tile score + e-phase, as a reusable lambda-ish ===============
    // (written inline twice per epoch)

    // =========================== prologue: epoch 0 ===========================
    {
        // issue v(0) -> slot 0, v(1) -> slot 1
        #pragma unroll
        for (int k = 0; k < 4; ++k) cp16(vs_base + voff[k], vg[k]);
        cp_commit();
        #pragma unroll
        for (int k = 0; k < 4; ++k) cp16(vs_base + VSLOTB + voff[k], vg[k] + VGT);
        cp_commit();

        // stage a2t tiles 0,1
        S.a2t[0][w][ac2] = a2row[ac2];
        S.a2t[1][w][ac2] = a2row[KT + ac2];
        __syncthreads();   // a2t 0,1 visible

        // prefetch a2 tiles 2,3 to regs
        float x0 = a2row[2 * KT + ac2];
        float x1 = a2row[3 * KT + ac2];

        // masks tiles 0,1
        int4 mq[2][2];
        #pragma unroll
        for (int i = 0; i < 2; ++i) {
            mq[0][i] = *(const int4*)(mbase + (size_t)(rp * 2 + i) * kL + cg * 4);
            mq[1][i] = *(const int4*)(mbase + (size_t)(rp * 2 + i) * kL + KT + cg * 4);
        }

        // scores + e for tiles 0 and 1
        #pragma unroll
        for (int tt = 0; tt < 2; ++tt) {
            const int j0 = tt * KT;
            ull sac[2][2];
            sac[0][0] = 0ULL; sac[0][1] = 0ULL;
            sac[1][0] = 0ULL; sac[1][1] = 0ULL;
            #pragma unroll
            for (int r = 0; r < kR; ++r) {
                ulonglong2 q = *(const ulonglong2*)&S.a2t[tt][r][cg * 4];
                #pragma unroll
                for (int i = 0; i < 2; ++i) {
                    ull ad = dup2(a1r[i][r]);
                    sac[i][0] = fma2(ad, q.x, sac[i][0]);
                    sac[i][1] = fma2(ad, q.y, sac[i][1]);
                }
            }
            #pragma unroll
            for (int i = 0; i < 2; ++i) {
                const int row = rp * 2 + i;
                const int4 m = mq[tt][i];
                float e0, e1, e2, e3;
                unpack2(sac[i][0], e0, e1);
                unpack2(sac[i][1], e2, e3);
                float4 e;
                e.x = m.x ? ex2(e0) : 0.f;
                e.y = m.y ? ex2(e1) : 0.f;
                e.z = m.z ? ex2(e2) : 0.f;
                e.w = m.w ? ex2(e3) : 0.f;
                rs[i] += (e.x + e.y) + (e.z + e.w);
                *(float4*)(attnbase + (size_t)row * kL + j0 + cg * 4) = e;
                uint4 u;
                u.x = f2tf32(e.x); u.y = f2tf32(e.y);
                u.z = f2tf32(e.z); u.w = f2tf32(e.w);
                *(uint4*)&S.p[tt][row][cg * 4] = u;
            }
        }

        // stage a2t tiles 2,3
        S.a2t[2][w][ac2] = x0;
        S.a2t[3][w][ac2] = x1;

        cp_wait0();        // v(0),v(1) resident
        __syncthreads();   // publish p[0],p[1], a2t[2],[3]
    }

    // ================= main epochs ep = 1..31 =================
    #pragma unroll 1
    for (int ep = 1; ep < NEP; ++ep) {
        const int jtA = 2 * ep;
        const int jtB = jtA + 1;
        const int sA  = jtA & 3;           // score tiles' slots
        const int sB  = jtB & 3;
        const int pA  = (jtA - 2) & 3;     // MMA tiles' slots
        const int pB  = (jtB - 2) & 3;

        // ---- issue v(jtA) -> slot sA, v(jtB) -> slot sB (freed at epoch ep-1) ----
        {
            const uint32_t ba = vs_base + (uint32_t)sA * VSLOTB;
            const size_t   ga = (size_t)jtA * VGT;
            #pragma unroll
            for (int k = 0; k < 4; ++k) cp16(ba + voff[k], vg[k] + ga);
            cp_commit();
            const uint32_t bb = vs_base + (uint32_t)sB * VSLOTB;
            const size_t   gb = (size_t)jtB * VGT;
            #pragma unroll
            for (int k = 0; k < 4; ++k) cp16(bb + voff[k], vg[k] + gb);
            cp_commit();
        }

        // ---- prefetch a2 tiles jtA+2, jtB+2 (clamped) ----
        const int jn0 = (jtA + 2 < NTILES) ? (jtA + 2) * KT : 0;
        const int jn1 = (jtB + 2 < NTILES) ? (jtB + 2) * KT : 0;
        float x0 = a2row[jn0 + ac2];
        float x1 = a2row[jn1 + ac2];

        // ---- masks for tiles jtA, jtB (consumed ~1K cyc later) ----
        int4 mq[2][2];
        #pragma unroll
        for (int i = 0; i < 2; ++i) {
            mq[0][i] = *(const int4*)(mbase + (size_t)(rp * 2 + i) * kL + jtA * KT + cg * 4);
            mq[1][i] = *(const int4*)(mbase + (size_t)(rp * 2 + i) * kL + jtB * KT + cg * 4);
        }

        // ---- scores for both tiles ----
        ull sacA[2][2], sacB[2][2];
        sacA[0][0] = 0ULL; sacA[0][1] = 0ULL; sacA[1][0] = 0ULL; sacA[1][1] = 0ULL;
        sacB[0][0] = 0ULL; sacB[0][1] = 0ULL; sacB[1][0] = 0ULL; sacB[1][1] = 0ULL;
        {
            const float* aA = (const float*)&S.a2t[sA][0][0];
            const float* aB = (const float*)&S.a2t[sB][0][0];
            #pragma unroll
            for (int r = 0; r < kR; ++r) {
                ulonglong2 qa = *(const ulonglong2*)(aA + (size_t)r * KT + cg * 4);
                ulonglong2 qb = *(const ulonglong2*)(aB + (size_t)r * KT + cg * 4);
                #pragma unroll
                for (int i = 0; i < 2; ++i) {
                    ull ad = dup2(a1r[i][r]);
                    sacA[i][0] = fma2(ad, qa.x, sacA[i][0]);
                    sacA[i][1] = fma2(ad, qa.y, sacA[i][1]);
                    sacB[i][0] = fma2(ad, qb.x, sacB[i][0]);
                    sacB[i][1] = fma2(ad, qb.y, sacB[i][1]);
                }
            }
        }

        // ---- MMA of previous epoch's tiles (independent: fills score->ex2 gap) ----
        mma_tile(acc, paddr0 + (uint32_t)pA * PBUFB, &S.v[pA][0][0], wn, qid, tig);
        mma_tile(acc, paddr0 + (uint32_t)pB * PBUFB, &S.v[pB][0][0], wn, qid, tig);

        // ---- e-phase for both tiles: attn STG + p STS ----
        #pragma unroll
        for (int i = 0; i < 2; ++i) {
            const int row = rp * 2 + i;
            float e0, e1, e2, e3;

            unpack2(sacA[i][0], e0, e1);
            unpack2(sacA[i][1], e2, e3);
            {
                const int4 m = mq[0][i];
                float4 e;
                e.x = m.x ? ex2(e0) : 0.f;
                e.y = m.y ? ex2(e1) : 0.f;
                e.z = m.z ? ex2(e2) : 0.f;
                e.w = m.w ? ex2(e3) : 0.f;
                rs[i] += (e.x + e.y) + (e.z + e.w);
                *(float4*)(attnbase + (size_t)row * kL + jtA * KT + cg * 4) = e;
                uint4 u;
                u.x = f2tf32(e.x); u.y = f2tf32(e.y);
                u.z = f2tf32(e.z); u.w = f2tf32(e.w);
                *(uint4*)&S.p[sA][row][cg * 4] = u;
            }

            unpack2(sacB[i][0], e0, e1);
            unpack2(sacB[i][1], e2, e3);
            {
                const int4 m = mq[1][i];
                float4 e;
                e.x = m.x ? ex2(e0) : 0.f;
                e.y = m.y ? ex2(e1) : 0.f;
                e.z = m.z ? ex2(e2) : 0.f;
                e.w = m.w ? ex2(e3) : 0.f;
                rs[i] += (e.x + e.y) + (e.z + e.w);
                *(float4*)(attnbase + (size_t)row * kL + jtB * KT + cg * 4) = e;
                uint4 u;
                u.x = f2tf32(e.x); u.y = f2tf32(e.y);
                u.z = f2tf32(e.z); u.w = f2tf32(e.w);
                *(uint4*)&S.p[sB][row][cg * 4] = u;
            }
        }

        // ---- stage a2t tiles jtA+2, jtB+2 into slots pA, pB (freed: scores ran ep-1) ----
        S.a2t[pA][w][ac2] = x0;
        S.a2t[pB][w][ac2] = x1;

        cp_wait0();        // v(jtA), v(jtB) resident (consumed next epoch)
        __syncthreads();   // publish p[sA],p[sB], a2t[pA],[pB], v slots
    }

    // ---- drain: MMA(62) slot 2, MMA(63) slot 3 ----
    mma_tile(acc, paddr0 + 2u * PBUFB, &S.v[2][0][0], wn, qid, tig);
    mma_tile(acc, paddr0 + 3u * PBUFB, &S.v[3][0][0], wn, qid, tig);

    // ---- rowsum reduce over 8 cg lanes (warp-local) ----
    float invr[2];
    #pragma unroll
    for (int i = 0; i < 2; ++i) {
        float r = rs[i];
        r += __shfl_xor_sync(0xffffffffu, r, 1);
        r += __shfl_xor_sync(0xffffffffu, r, 2);
        r += __shfl_xor_sync(0xffffffffu, r, 4);
        invr[i] = 1.0f / r;
        if (cg == 0) S.inv[rp * 2 + i] = invr[i];
    }
    __syncthreads();

    // ---- out epilogue: scale accumulators by row inv ----
    #pragma unroll
    for (int mt = 0; mt < 2; ++mt) {
        const int row0 = 32 * wm + 16 * mt + qid;
        const float ivlo = S.inv[row0];
        const float ivhi = S.inv[row0 + 8];
        #pragma unroll
        for (int nt = 0; nt < 4; ++nt) {
            const int col = 32 * wn + 8 * nt + 2 * tig;
            float2 lo; lo.x = acc[mt][nt][0] * ivlo; lo.y = acc[mt][nt][1] * ivlo;
            float2 hi; hi.x = acc[mt][nt][2] * ivhi; hi.y = acc[mt][nt][3] * ivhi;
            *(float2*)(outbase + (size_t)row0 * kDV + col)       = lo;
            *(float2*)(outbase + (size_t)(row0 + 8) * kDV + col) = hi;
        }
    }

    // ---- attn rescale: both rows interleaved for 2x MLP ----
    {
        float* ap0 = attnbase + (size_t)(rp * 2 + 0) * kL + cg * 4;
        float* ap1 = attnbase + (size_t)(rp * 2 + 1) * kL + cg * 4;
        const float iv0 = invr[0];
        const float iv1 = invr[1];
        #pragma unroll 4
        for (int jt = 0; jt < NTILES; jt += 2) {
            float4 e00 = *(const float4*)(ap0 + jt * KT);
            float4 e01 = *(const float4*)(ap0 + (jt + 1) * KT);
            float4 e10 = *(const float4*)(ap1 + jt * KT);
            float4 e11 = *(const float4*)(ap1 + (jt + 1) * KT);
            e00.x *= iv0; e00.y *= iv0; e00.z *= iv0; e00.w *= iv0;
            e01.x *= iv0; e01.y *= iv0; e01.z *= iv0; e01.w *= iv0;
            e10.x *= iv1; e10.y *= iv1; e10.z *= iv1; e10.w *= iv1;
            e11.x *= iv1; e11.y *= iv1; e11.z *= iv1; e11.w *= iv1;
            *(float4*)(ap0 + jt * KT)       = e00;
            *(float4*)(ap0 + (jt + 1) * KT) = e01;
            *(float4*)(ap1 + jt * KT)       = e10;
            *(float4*)(ap1 + (jt + 1) * KT) = e11;
        }
    }
}

} // namespace

extern "C" void kernel_launch(void* const* d_in, const int* in_sizes, int n_in,
                              void* d_out, int out_size) {
    const float* v    = (const float*)d_in[0];
    const float* a1   = (const float*)d_in[1];
    const float* a2   = (const float*)d_in[2];
    const int*   mask = (const int*)d_in[3];

    float* out  = (float*)d_out;
    float* attn = out + (size_t)kB * kH * kL * kDV;

    const int smem = (int)sizeof(SmemLayout);
    cudaFuncSetAttribute(fra_kernel, cudaFuncAttributeMaxDynamicSharedMemorySize, smem);

    dim3 grid(kH, kL / TM, kB);   // heads fastest -> mask tile L2 reuse across 8 heads
    fra_kernel<<<grid, NT, smem>>>(v, a1, a2, mask, out, attn);
}

// round 15
// speedup vs baseline: 1.2386x; 1.2386x over previous
#include <cuda_runtime.h>
#include <cstdint>
#include <cstddef>

namespace {

constexpr int kB  = 4;
constexpr int kH  = 8;
constexpr int kL  = 2048;
constexpr int kR  = 8;
constexpr int kDV = 128;

constexpr int TM = 64;           // rows per CTA
constexpr int KT = 32;           // K-tile
constexpr int NT = 256;          // threads
constexpr int NTILES = kL / KT;  // 64
constexpr int NWORDS = kL / 32;  // 64 mask words per row

constexpr int PSTRIDE = 36;      // p row stride (u32): ldmatrix rows hit distinct 16B groups
constexpr int VSTRIDE = 136;     // v row stride (u32): B-frag conflict-free
constexpr float kLog2e = 1.44269504088896340736f;

typedef unsigned long long ull;

// bit-packed mask scratch: [b][row][word]  (2 MB)
__device__ uint32_t g_maskbits[kB * kL * NWORDS];

__device__ __forceinline__ ull dup2(float x) {
    ull r; asm("mov.b64 %0, {%1,%1};" : "=l"(r) : "f"(x)); return r;
}
__device__ __forceinline__ void unpack2(ull v, float& lo, float& hi) {
    asm("mov.b64 {%0,%1}, %2;" : "=f"(lo), "=f"(hi) : "l"(v));
}
__device__ __forceinline__ ull fma2(ull a, ull b, ull c) {
    ull d; asm("fma.rn.f32x2 %0, %1, %2, %3;" : "=l"(d) : "l"(a), "l"(b), "l"(c));
    return d;
}
__device__ __forceinline__ uint32_t f2tf32(float x) {
    uint32_t r; asm("cvt.rna.tf32.f32 %0, %1;" : "=r"(r) : "f"(x)); return r;
}
__device__ __forceinline__ float ex2(float x) {
    float r; asm("ex2.approx.f32 %0, %1;" : "=f"(r) : "f"(x)); return r;
}
__device__ __forceinline__ void mma_tf32(float d[4], const uint32_t a[4],
                                         uint32_t b0, uint32_t b1) {
    asm volatile(
        "mma.sync.aligned.m16n8k8.row.col.f32.tf32.tf32.f32 "
        "{%0,%1,%2,%3}, {%4,%5,%6,%7}, {%8,%9}, {%0,%1,%2,%3};"
        : "+f"(d[0]), "+f"(d[1]), "+f"(d[2]), "+f"(d[3])
        : "r"(a[0]), "r"(a[1]), "r"(a[2]), "r"(a[3]), "r"(b0), "r"(b1));
}
__device__ __forceinline__ void ldmatrix_x4(uint32_t a[4], uint32_t addr) {
    asm volatile(
        "ldmatrix.sync.aligned.m8n8.x4.shared.b16 {%0,%1,%2,%3}, [%4];"
        : "=r"(a[0]), "=r"(a[1]), "=r"(a[2]), "=r"(a[3]) : "r"(addr));
}
__device__ __forceinline__ uint32_t smem_u32(const void* p) {
    uint32_t a;
    asm("{ .reg .u64 t; cvta.to.shared.u64 t, %1; cvt.u32.u64 %0, t; }"
        : "=r"(a) : "l"(p));
    return a;
}
__device__ __forceinline__ void cp16(uint32_t saddr, const void* g) {
    asm volatile("cp.async.ca.shared.global [%0], [%1], 16;"
                 :: "r"(saddr), "l"(g) : "memory");
}
__device__ __forceinline__ void cp_commit() {
    asm volatile("cp.async.commit_group;" ::: "memory");
}
__device__ __forceinline__ void cp_wait1() {
    asm volatile("cp.async.wait_group 1;" ::: "memory");
}

// ---------------- mask bit-pack pre-pass ----------------
__global__ void __launch_bounds__(256)
pack_mask_kernel(const int* __restrict__ mask) {
    const int idx = blockIdx.x * 256 + threadIdx.x;   // [0, kB*kL*NWORDS)
    const int4* src = (const int4*)(mask + (size_t)idx * 32);
    uint32_t bits = 0;
    #pragma unroll
    for (int k = 0; k < 8; ++k) {
        int4 m = src[k];
        bits |= (m.x ? 1u : 0u) << (4 * k + 0);
        bits |= (m.y ? 1u : 0u) << (4 * k + 1);
        bits |= (m.z ? 1u : 0u) << (4 * k + 2);
        bits |= (m.w ? 1u : 0u) << (4 * k + 3);
    }
    g_maskbits[idx] = bits;
}

struct __align__(16) SmemLayout {
    uint32_t p[2][TM][PSTRIDE];    // 18.4 KB (tf32 E tiles, double buffered)
    uint32_t v[3][KT][VSTRIDE];    // 52.2 KB (raw f32 v tiles, cp.async ring)
    float    a2t[2][kR][KT];       // 2 KB   (streamed a2 K-tiles)
    float    inv[TM];              // 256 B
};
// ~73 KB -> 2 CTAs/SM

__global__ void __launch_bounds__(NT, 2)
fra_kernel(const float* __restrict__ gv,
           const float* __restrict__ ga1,
           const float* __restrict__ ga2,
           float* __restrict__ gout,
           float* __restrict__ gattn)
{
    extern __shared__ char smem_raw[];
    SmemLayout& S = *reinterpret_cast<SmemLayout*>(smem_raw);

    const int h    = blockIdx.x;   // heads fastest: 8 heads share mask words in L2
    const int tile = blockIdx.y;
    const int b    = blockIdx.z;
    const int bh   = b * kH + h;
    const int i0g  = tile * TM;
    const int t    = threadIdx.x;
    const int w    = t >> 5;
    const int l    = t & 31;

    const float* a2base = ga2 + (size_t)bh * kR * kL;
    const float* a1base = ga1 + ((size_t)bh * kL + i0g) * kR;
    const float* vbase  = gv  + (size_t)bh * kL * kDV;
    const uint32_t* mwb = g_maskbits + (size_t)(b * kL + i0g) * NWORDS;
    float* attnbase = gattn + ((size_t)bh * kL + i0g) * kL;
    float* outbase  = gout  + ((size_t)bh * kL + i0g) * kDV;

    // score mapping: rows 2*rp+i (i=0,1), cols cg*4 within K-tile
    const int rp = t >> 3;   // 0..31
    const int cg = t & 7;    // 0..7

    // a1 (pre-scaled by log2e for ex2) for this thread's 2 rows
    float a1r[2][kR];
    #pragma unroll
    for (int i = 0; i < 2; ++i) {
        const float4* src = (const float4*)(a1base + (size_t)(rp * 2 + i) * kR);
        float4 q0 = src[0], q1 = src[1];
        a1r[i][0] = q0.x * kLog2e; a1r[i][1] = q0.y * kLog2e;
        a1r[i][2] = q0.z * kLog2e; a1r[i][3] = q0.w * kLog2e;
        a1r[i][4] = q1.x * kLog2e; a1r[i][5] = q1.y * kLog2e;
        a1r[i][6] = q1.z * kLog2e; a1r[i][7] = q1.w * kLog2e;
    }

    // GEMM warp grid 2x4 (wm x wn); warp tile 32 rows x 32 cols
    const int wm  = w >> 2;
    const int wn  = w & 3;
    const int qid = l >> 2;
    const int tig = l & 3;

    // ldmatrix A lane address
    const int lrow = 32 * wm + ((l >> 3) & 1) * 8 + (l & 7);
    const int lcol = ((l >> 4) & 1) * 4;
    uint32_t paddr[2];
    paddr[0] = smem_u32(&S.p[0][lrow][lcol]);
    paddr[1] = smem_u32(&S.p[1][lrow][lcol]);

    float acc[2][4][4];
    #pragma unroll
    for (int mt = 0; mt < 2; ++mt)
        #pragma unroll
        for (int nt = 0; nt < 4; ++nt)
            #pragma unroll
            for (int e = 0; e < 4; ++e) acc[mt][nt][e] = 0.f;

    float rs[2] = {0.f, 0.f};

    // ---- cp.async v addressing ----
    const uint32_t vs_base = smem_u32(&S.v[0][0][0]);
    uint32_t voff[4];
    #pragma unroll
    for (int k = 0; k < 4; ++k)
        voff[k] = (uint32_t)(((w + 8 * k) * VSTRIDE + 4 * l) * 4);
    const float* vg[4];
    #pragma unroll
    for (int k = 0; k < 4; ++k)
        vg[k] = vbase + (size_t)(w + 8 * k) * kDV + 4 * l;
    constexpr uint32_t VSLOT = KT * VSTRIDE * 4;
    constexpr size_t   VGT   = (size_t)KT * kDV;

    // balanced a2 staging: 1 float per thread (warp w -> a2 row w, col l)
    const int ar2 = w;          // a2 row 0..7
    const int ac2 = l;          // col within tile 0..31
    const float* a2row = a2base + (size_t)ar2 * kL;

    uint32_t mw[2][2];   // mask words: [tile parity][row i]

    // =========================== prologue + peeled jt = 0 ===========================
    {
        // v tile 0 -> slot 0
        #pragma unroll
        for (int k = 0; k < 4; ++k) cp16(vs_base + voff[k], vg[k]);
        cp_commit();

        S.a2t[0][ar2][ac2] = a2row[ac2];

        #pragma unroll
        for (int i = 0; i < 2; ++i) {
            mw[0][i] = mwb[(size_t)(rp * 2 + i) * NWORDS + 0];
            mw[1][i] = mwb[(size_t)(rp * 2 + i) * NWORDS + 1];
        }
        __syncthreads();   // a2t[0] visible

        // v tile 1 -> slot 1
        {
            const uint32_t sb = vs_base + VSLOT;
            #pragma unroll
            for (int k = 0; k < 4; ++k) cp16(sb + voff[k], vg[k] + VGT);
            cp_commit();
        }
        float a2n = a2row[KT + ac2];

        // scores tile 0
        ull sac[2][2];
        sac[0][0] = 0ULL; sac[0][1] = 0ULL;
        sac[1][0] = 0ULL; sac[1][1] = 0ULL;
        #pragma unroll
        for (int r = 0; r < kR; ++r) {
            ulonglong2 q = *(const ulonglong2*)&S.a2t[0][r][cg * 4];
            #pragma unroll
            for (int i = 0; i < 2; ++i) {
                ull ad = dup2(a1r[i][r]);
                sac[i][0] = fma2(ad, q.x, sac[i][0]);
                sac[i][1] = fma2(ad, q.y, sac[i][1]);
            }
        }
        #pragma unroll
        for (int i = 0; i < 2; ++i) {
            const int row = rp * 2 + i;
            const uint32_t mb = mw[0][i] >> (cg * 4);
            float e0, e1, e2, e3;
            unpack2(sac[i][0], e0, e1);
            unpack2(sac[i][1], e2, e3);
            float4 e;
            e.x = (mb & 1u) ? ex2(e0) : 0.f;
            e.y = (mb & 2u) ? ex2(e1) : 0.f;
            e.z = (mb & 4u) ? ex2(e2) : 0.f;
            e.w = (mb & 8u) ? ex2(e3) : 0.f;
            rs[i] += (e.x + e.y) + (e.z + e.w);
            *(float4*)(attnbase + (size_t)row * kL + cg * 4) = e;
            uint4 u;
            u.x = f2tf32(e.x); u.y = f2tf32(e.y);
            u.z = f2tf32(e.z); u.w = f2tf32(e.w);
            *(uint4*)&S.p[0][row][cg * 4] = u;
        }
        // mask words tile 2 -> slot 0
        #pragma unroll
        for (int i = 0; i < 2; ++i)
            mw[0][i] = mwb[(size_t)(rp * 2 + i) * NWORDS + 2];
        S.a2t[1][ar2][ac2] = a2n;

        cp_wait1();        // v tile 0 resident
        __syncthreads();   // publish p[0]/a2t[1]/v(0)
    }

    // ================= main loop jt = 1..63: score(jt) + MMA(jt-1) same epoch =================
    int sprev = 0, snxt = 2;
    #pragma unroll 2
    for (int jt = 1; jt < NTILES; ++jt) {
        const int buf = jt & 1;
        const int j0  = jt * KT;

        // ---- issue cp.async for v tile jt+1 into slot snxt ----
        {
            const size_t goff = (jt + 1 < NTILES) ? (size_t)(jt + 1) * VGT : 0;
            const uint32_t sb = vs_base + (uint32_t)snxt * VSLOT;
            #pragma unroll
            for (int k = 0; k < 4; ++k) cp16(sb + voff[k], vg[k] + goff);
            cp_commit();
        }

        // ---- prefetch next a2 tile (1 float/thread) ----
        const int jn = (jt + 1 < NTILES) ? j0 + KT : 0;
        float a2n = a2row[jn + ac2];

        // ---- scores(jt): LDS a2t[buf] + fma2 ----
        ull sac[2][2];
        sac[0][0] = 0ULL; sac[0][1] = 0ULL;
        sac[1][0] = 0ULL; sac[1][1] = 0ULL;
        #pragma unroll
        for (int r = 0; r < kR; ++r) {
            ulonglong2 q = *(const ulonglong2*)&S.a2t[buf][r][cg * 4];
            #pragma unroll
            for (int i = 0; i < 2; ++i) {
                ull ad = dup2(a1r[i][r]);
                sac[i][0] = fma2(ad, q.x, sac[i][0]);
                sac[i][1] = fma2(ad, q.y, sac[i][1]);
            }
        }

        // ---- MMA(jt-1): p[buf^1], v slot sprev — same epoch, interleaves with above ----
        {
            const uint32_t* vt = &S.v[sprev][0][0];
            const uint32_t ab = paddr[buf ^ 1];
            #pragma unroll
            for (int s = 0; s < 4; ++s) {
                uint32_t a[2][4];
                ldmatrix_x4(a[0], ab + (uint32_t)(s * 32));
                ldmatrix_x4(a[1], ab + (uint32_t)(16 * PSTRIDE * 4 + s * 32));
                #pragma unroll
                for (int nt = 0; nt < 4; ++nt) {
                    const int n = 32 * wn + 8 * nt + qid;
                    uint32_t b0 = vt[(size_t)(8 * s + tig) * VSTRIDE + n];
                    uint32_t b1 = vt[(size_t)(8 * s + 4 + tig) * VSTRIDE + n];
                    mma_tf32(acc[0][nt], a[0], b0, b1);
                    mma_tf32(acc[1][nt], a[1], b0, b1);
                }
            }
        }

        // ---- e = mask*exp2(s): attn STG, rowsum, p STS (tf32) ----
        #pragma unroll
        for (int i = 0; i < 2; ++i) {
            const int row = rp * 2 + i;
            const uint32_t mb = mw[buf][i] >> (cg * 4);
            float e0, e1, e2, e3;
            unpack2(sac[i][0], e0, e1);
            unpack2(sac[i][1], e2, e3);
            float4 e;
            e.x = (mb & 1u) ? ex2(e0) : 0.f;
            e.y = (mb & 2u) ? ex2(e1) : 0.f;
            e.z = (mb & 4u) ? ex2(e2) : 0.f;
            e.w = (mb & 8u) ? ex2(e3) : 0.f;
            rs[i] += (e.x + e.y) + (e.z + e.w);
            *(float4*)(attnbase + (size_t)row * kL + j0 + cg * 4) = e;
            uint4 u;
            u.x = f2tf32(e.x); u.y = f2tf32(e.y);
            u.z = f2tf32(e.z); u.w = f2tf32(e.w);
            *(uint4*)&S.p[buf][row][cg * 4] = u;
        }

        // ---- mask-word prefetch 2 tiles ahead ----
        {
            const int jm = (jt + 2 < NTILES) ? (jt + 2) : 0;
            #pragma unroll
            for (int i = 0; i < 2; ++i)
                mw[buf][i] = mwb[(size_t)(rp * 2 + i) * NWORDS + jm];
        }

        // ---- stage next a2 tile ----
        S.a2t[buf ^ 1][ar2][ac2] = a2n;

        cp_wait1();        // v tile jt resident (only jt+1 pending)
        __syncthreads();   // publish p[buf]/a2t[buf^1]/v(jt)

        sprev = (sprev == 2) ? 0 : sprev + 1;
        snxt  = (snxt  == 2) ? 0 : snxt  + 1;
    }

    // ---- drain: MMA(63): p[1], v slot 63%3 = 0 ----
    {
        const uint32_t* vt = &S.v[sprev][0][0];
        const uint32_t ab = paddr[1];
        #pragma unroll
        for (int s = 0; s < 4; ++s) {
            uint32_t a[2][4];
            ldmatrix_x4(a[0], ab + (uint32_t)(s * 32));
            ldmatrix_x4(a[1], ab + (uint32_t)(16 * PSTRIDE * 4 + s * 32));
            #pragma unroll
            for (int nt = 0; nt < 4; ++nt) {
                const int n = 32 * wn + 8 * nt + qid;
                uint32_t b0 = vt[(size_t)(8 * s + tig) * VSTRIDE + n];
                uint32_t b1 = vt[(size_t)(8 * s + 4 + tig) * VSTRIDE + n];
                mma_tf32(acc[0][nt], a[0], b0, b1);
                mma_tf32(acc[1][nt], a[1], b0, b1);
            }
        }
    }

    // ---- rowsum reduce over 8 cg lanes (warp-local) ----
    float invr[2];
    #pragma unroll
    for (int i = 0; i < 2; ++i) {
        float r = rs[i];
        r += __shfl_xor_sync(0xffffffffu, r, 1);
        r += __shfl_xor_sync(0xffffffffu, r, 2);
        r += __shfl_xor_sync(0xffffffffu, r, 4);
        invr[i] = 1.0f / r;
        if (cg == 0) S.inv[rp * 2 + i] = invr[i];
    }
    __syncthreads();

    // ---- out epilogue: scale accumulators by row inv ----
    #pragma unroll
    for (int mt = 0; mt < 2; ++mt) {
        const int row0 = 32 * wm + 16 * mt + qid;
        const float ivlo = S.inv[row0];
        const float ivhi = S.inv[row0 + 8];
        #pragma unroll
        for (int nt = 0; nt < 4; ++nt) {
            const int col = 32 * wn + 8 * nt + 2 * tig;
            float2 lo; lo.x = acc[mt][nt][0] * ivlo; lo.y = acc[mt][nt][1] * ivlo;
            float2 hi; hi.x = acc[mt][nt][2] * ivhi; hi.y = acc[mt][nt][3] * ivhi;
            *(float2*)(outbase + (size_t)row0 * kDV + col)       = lo;
            *(float2*)(outbase + (size_t)(row0 + 8) * kDV + col) = hi;
        }
    }

    // ---- attn rescale: each thread rescales exactly the float4s it wrote ----
    #pragma unroll
    for (int i = 0; i < 2; ++i) {
        float* aprow = attnbase + (size_t)(rp * 2 + i) * kL + cg * 4;
        const float iv = invr[i];
        #pragma unroll 8
        for (int jt = 0; jt < NTILES; ++jt) {
            float4 e = *(const float4*)(aprow + jt * KT);
            e.x *= iv; e.y *= iv; e.z *= iv; e.w *= iv;
            *(float4*)(aprow + jt * KT) = e;
        }
    }
}

} // namespace

extern "C" void kernel_launch(void* const* d_in, const int* in_sizes, int n_in,
                              void* d_out, int out_size) {
    const float* v    = (const float*)d_in[0];
    const float* a1   = (const float*)d_in[1];
    const float* a2   = (const float*)d_in[2];
    const int*   mask = (const int*)d_in[3];

    float* out  = (float*)d_out;
    float* attn = out + (size_t)kB * kH * kL * kDV;

    // pre-pass: bit-pack the mask (2 MB scratch, ~15 us)
    pack_mask_kernel<<<kB * kL * NWORDS / 256, 256>>>(mask);

    const int smem = (int)sizeof(SmemLayout);
    cudaFuncSetAttribute(fra_kernel, cudaFuncAttributeMaxDynamicSharedMemorySize, smem);

    dim3 grid(kH, kL / TM, kB);   // heads fastest -> mask words L2-resident across 8 heads
    fra_kernel<<<grid, NT, smem>>>(v, a1, a2, out, attn);
}

// round 16
// speedup vs baseline: 1.3139x; 1.0608x over previous
#include <cuda_runtime.h>
#include <cstdint>
#include <cstddef>

namespace {

constexpr int kB  = 4;
constexpr int kH  = 8;
constexpr int kL  = 2048;
constexpr int kR  = 8;
constexpr int kDV = 128;

constexpr int TM = 64;           // rows per CTA
constexpr int KT = 32;           // K-tile
constexpr int NT = 256;          // threads
constexpr int NTILES = kL / KT;  // 64

constexpr int PSTRIDE = 36;      // p row stride (u32): ldmatrix rows hit distinct 16B groups
constexpr int VSTRIDE = 136;     // v row stride (u32): B-frag conflict-free
constexpr float kLog2e = 1.44269504088896340736f;

typedef unsigned long long ull;

__device__ __forceinline__ ull dup2(float x) {
    ull r; asm("mov.b64 %0, {%1,%1};" : "=l"(r) : "f"(x)); return r;
}
__device__ __forceinline__ void unpack2(ull v, float& lo, float& hi) {
    asm("mov.b64 {%0,%1}, %2;" : "=f"(lo), "=f"(hi) : "l"(v));
}
__device__ __forceinline__ ull fma2(ull a, ull b, ull c) {
    ull d; asm("fma.rn.f32x2 %0, %1, %2, %3;" : "=l"(d) : "l"(a), "l"(b), "l"(c));
    return d;
}
__device__ __forceinline__ uint32_t f2tf32(float x) {
    uint32_t r; asm("cvt.rna.tf32.f32 %0, %1;" : "=r"(r) : "f"(x)); return r;
}
__device__ __forceinline__ float ex2(float x) {
    float r; asm("ex2.approx.f32 %0, %1;" : "=f"(r) : "f"(x)); return r;
}
// NON-volatile: pure register dataflow -> compiler may interleave HMMA with
// score fma2/ex2 streams (the intra-warp overlap the epoch fusion wants).
__device__ __forceinline__ void mma_tf32(float d[4], const uint32_t a[4],
                                         uint32_t b0, uint32_t b1) {
    asm("mma.sync.aligned.m16n8k8.row.col.f32.tf32.tf32.f32 "
        "{%0,%1,%2,%3}, {%4,%5,%6,%7}, {%8,%9}, {%0,%1,%2,%3};"
        : "+f"(d[0]), "+f"(d[1]), "+f"(d[2]), "+f"(d[3])
        : "r"(a[0]), "r"(a[1]), "r"(a[2]), "r"(a[3]), "r"(b0), "r"(b1));
}
// Non-volatile but with memory clobber: can't cross __syncthreads/STS,
// CAN interleave with arithmetic.
__device__ __forceinline__ void ldmatrix_x4(uint32_t a[4], uint32_t addr) {
    asm("ldmatrix.sync.aligned.m8n8.x4.shared.b16 {%0,%1,%2,%3}, [%4];"
        : "=r"(a[0]), "=r"(a[1]), "=r"(a[2]), "=r"(a[3]) : "r"(addr) : "memory");
}
__device__ __forceinline__ uint32_t smem_u32(const void* p) {
    uint32_t a;
    asm("{ .reg .u64 t; cvta.to.shared.u64 t, %1; cvt.u32.u64 %0, t; }"
        : "=r"(a) : "l"(p));
    return a;
}
__device__ __forceinline__ void cp16(uint32_t saddr, const void* g) {
    asm volatile("cp.async.ca.shared.global [%0], [%1], 16;"
                 :: "r"(saddr), "l"(g) : "memory");
}
__device__ __forceinline__ void cp_commit() {
    asm volatile("cp.async.commit_group;" ::: "memory");
}
__device__ __forceinline__ void cp_wait1() {
    asm volatile("cp.async.wait_group 1;" ::: "memory");
}

struct __align__(16) SmemLayout {
    uint32_t p[2][TM][PSTRIDE];    // 18.4 KB (tf32 E tiles, double buffered)
    uint32_t v[3][KT][VSTRIDE];    // 52.2 KB (raw f32 v tiles, cp.async ring)
    float    a2t[2][kR][KT];       // 2 KB   (streamed a2 K-tiles)
    float    inv[TM];              // 256 B
};
// ~73 KB -> 2 CTAs/SM

__global__ void __launch_bounds__(NT, 2)
fra_kernel(const float* __restrict__ gv,
           const float* __restrict__ ga1,
           const float* __restrict__ ga2,
           const int*   __restrict__ gmask,
           float* __restrict__ gout,
           float* __restrict__ gattn)
{
    extern __shared__ char smem_raw[];
    SmemLayout& S = *reinterpret_cast<SmemLayout*>(smem_raw);

    const int h    = blockIdx.x;   // heads fastest: 8 heads share mask tile in L2
    const int tile = blockIdx.y;
    const int b    = blockIdx.z;
    const int bh   = b * kH + h;
    const int i0g  = tile * TM;
    const int t    = threadIdx.x;
    const int w    = t >> 5;
    const int l    = t & 31;

    const float* a2base = ga2 + (size_t)bh * kR * kL;
    const float* a1base = ga1 + ((size_t)bh * kL + i0g) * kR;
    const float* vbase  = gv  + (size_t)bh * kL * kDV;
    const int*   mbase  = gmask + ((size_t)b * kL + i0g) * kL;
    float* attnbase = gattn + ((size_t)bh * kL + i0g) * kL;
    float* outbase  = gout  + ((size_t)bh * kL + i0g) * kDV;

    // score mapping: rows 2*rp+i (i=0,1), cols cg*4 within K-tile
    const int rp = t >> 3;   // 0..31
    const int cg = t & 7;    // 0..7

    // a1 (pre-scaled by log2e for ex2) for this thread's 2 rows
    float a1r[2][kR];
    #pragma unroll
    for (int i = 0; i < 2; ++i) {
        const float4* src = (const float4*)(a1base + (size_t)(rp * 2 + i) * kR);
        float4 q0 = src[0], q1 = src[1];
        a1r[i][0] = q0.x * kLog2e; a1r[i][1] = q0.y * kLog2e;
        a1r[i][2] = q0.z * kLog2e; a1r[i][3] = q0.w * kLog2e;
        a1r[i][4] = q1.x * kLog2e; a1r[i][5] = q1.y * kLog2e;
        a1r[i][6] = q1.z * kLog2e; a1r[i][7] = q1.w * kLog2e;
    }

    // GEMM warp grid 2x4 (wm x wn); warp tile 32 rows x 32 cols
    const int wm  = w >> 2;
    const int wn  = w & 3;
    const int qid = l >> 2;
    const int tig = l & 3;

    // ldmatrix A lane address
    const int lrow = 32 * wm + ((l >> 3) & 1) * 8 + (l & 7);
    const int lcol = ((l >> 4) & 1) * 4;
    uint32_t paddr[2];
    paddr[0] = smem_u32(&S.p[0][lrow][lcol]);
    paddr[1] = smem_u32(&S.p[1][lrow][lcol]);

    float acc[2][4][4];
    #pragma unroll
    for (int mt = 0; mt < 2; ++mt)
        #pragma unroll
        for (int nt = 0; nt < 4; ++nt)
            #pragma unroll
            for (int e = 0; e < 4; ++e) acc[mt][nt][e] = 0.f;

    float rs[2] = {0.f, 0.f};

    // ---- cp.async v addressing ----
    const uint32_t vs_base = smem_u32(&S.v[0][0][0]);
    uint32_t voff[4];
    #pragma unroll
    for (int k = 0; k < 4; ++k)
        voff[k] = (uint32_t)(((w + 8 * k) * VSTRIDE + 4 * l) * 4);
    const float* vg[4];
    #pragma unroll
    for (int k = 0; k < 4; ++k)
        vg[k] = vbase + (size_t)(w + 8 * k) * kDV + 4 * l;
    constexpr uint32_t VSLOT = KT * VSTRIDE * 4;
    constexpr size_t   VGT   = (size_t)KT * kDV;

    const int ar = t >> 3;
    const int ac = t & 7;

    int4 mq_buf[2][2];

    // =========================== prologue + peeled jt = 0 ===========================
    {
        // v tile 0 -> slot 0
        #pragma unroll
        for (int k = 0; k < 4; ++k) cp16(vs_base + voff[k], vg[k]);
        cp_commit();

        if (t < 64)
            *(float4*)&S.a2t[0][ar][ac * 4] =
                *(const float4*)(a2base + (size_t)ar * kL + ac * 4);

        #pragma unroll
        for (int i = 0; i < 2; ++i) {
            mq_buf[0][i] = *(const int4*)(mbase + (size_t)(rp * 2 + i) * kL + cg * 4);
            mq_buf[1][i] = *(const int4*)(mbase + (size_t)(rp * 2 + i) * kL + KT + cg * 4);
        }
        __syncthreads();   // a2t[0] visible

        // v tile 1 -> slot 1
        {
            const uint32_t sb = vs_base + VSLOT;
            #pragma unroll
            for (int k = 0; k < 4; ++k) cp16(sb + voff[k], vg[k] + VGT);
            cp_commit();
        }
        float4 a2n;
        if (t < 64)
            a2n = *(const float4*)(a2base + (size_t)ar * kL + KT + ac * 4);

        // scores tile 0
        ull sac[2][2];
        sac[0][0] = 0ULL; sac[0][1] = 0ULL;
        sac[1][0] = 0ULL; sac[1][1] = 0ULL;
        #pragma unroll
        for (int r = 0; r < kR; ++r) {
            ulonglong2 q = *(const ulonglong2*)&S.a2t[0][r][cg * 4];
            #pragma unroll
            for (int i = 0; i < 2; ++i) {
                ull ad = dup2(a1r[i][r]);
                sac[i][0] = fma2(ad, q.x, sac[i][0]);
                sac[i][1] = fma2(ad, q.y, sac[i][1]);
            }
        }
        #pragma unroll
        for (int i = 0; i < 2; ++i) {
            const int row = rp * 2 + i;
            const int4 m = mq_buf[0][i];
            float e0, e1, e2, e3;
            unpack2(sac[i][0], e0, e1);
            unpack2(sac[i][1], e2, e3);
            float4 e;
            e.x = m.x ? ex2(e0) : 0.f;
            e.y = m.y ? ex2(e1) : 0.f;
            e.z = m.z ? ex2(e2) : 0.f;
            e.w = m.w ? ex2(e3) : 0.f;
            rs[i] += (e.x + e.y) + (e.z + e.w);
            *(float4*)(attnbase + (size_t)row * kL + cg * 4) = e;
            uint4 u;
            u.x = f2tf32(e.x); u.y = f2tf32(e.y);
            u.z = f2tf32(e.z); u.w = f2tf32(e.w);
            *(uint4*)&S.p[0][row][cg * 4] = u;
        }
        // mask tile 2 -> slot 0
        #pragma unroll
        for (int i = 0; i < 2; ++i)
            mq_buf[0][i] = *(const int4*)(mbase + (size_t)(rp * 2 + i) * kL + 2 * KT + cg * 4);
        if (t < 64)
            *(float4*)&S.a2t[1][ar][ac * 4] = a2n;

        cp_wait1();        // v tile 0 resident
        __syncthreads();   // publish p[0]/a2t[1]/v(0)
    }

    // ================= main loop jt = 1..63: score(jt) + MMA(jt-1) same epoch =================
    int sprev = 0, snxt = 2;
    #pragma unroll 2
    for (int jt = 1; jt < NTILES; ++jt) {
        const int buf = jt & 1;
        const int j0  = jt * KT;

        // ---- issue cp.async for v tile jt+1 into slot snxt ----
        {
            const size_t goff = (jt + 1 < NTILES) ? (size_t)(jt + 1) * VGT : 0;
            const uint32_t sb = vs_base + (uint32_t)snxt * VSLOT;
            #pragma unroll
            for (int k = 0; k < 4; ++k) cp16(sb + voff[k], vg[k] + goff);
            cp_commit();
        }

        // ---- prefetch next a2 tile ----
        float4 a2n;
        const int jn = (jt + 1 < NTILES) ? j0 + KT : 0;
        if (t < 64)
            a2n = *(const float4*)(a2base + (size_t)ar * kL + jn + ac * 4);

        // ---- scores(jt): LDS a2t[buf] + fma2 ----
        ull sac[2][2];
        sac[0][0] = 0ULL; sac[0][1] = 0ULL;
        sac[1][0] = 0ULL; sac[1][1] = 0ULL;
        #pragma unroll
        for (int r = 0; r < kR; ++r) {
            ulonglong2 q = *(const ulonglong2*)&S.a2t[buf][r][cg * 4];
            #pragma unroll
            for (int i = 0; i < 2; ++i) {
                ull ad = dup2(a1r[i][r]);
                sac[i][0] = fma2(ad, q.x, sac[i][0]);
                sac[i][1] = fma2(ad, q.y, sac[i][1]);
            }
        }

        // ---- MMA(jt-1): p[buf^1], v slot sprev — interleaves with scores/e-phase ----
        {
            const uint32_t* vt = &S.v[sprev][0][0];
            const uint32_t ab = paddr[buf ^ 1];
            #pragma unroll
            for (int s = 0; s < 4; ++s) {
                uint32_t a[2][4];
                ldmatrix_x4(a[0], ab + (uint32_t)(s * 32));
                ldmatrix_x4(a[1], ab + (uint32_t)(16 * PSTRIDE * 4 + s * 32));
                #pragma unroll
                for (int nt = 0; nt < 4; ++nt) {
                    const int n = 32 * wn + 8 * nt + qid;
                    uint32_t b0 = vt[(size_t)(8 * s + tig) * VSTRIDE + n];
                    uint32_t b1 = vt[(size_t)(8 * s + 4 + tig) * VSTRIDE + n];
                    mma_tf32(acc[0][nt], a[0], b0, b1);
                    mma_tf32(acc[1][nt], a[1], b0, b1);
                }
            }
        }

        // ---- e = mask*exp2(s): attn STG, rowsum, p STS (tf32) ----
        #pragma unroll
        for (int i = 0; i < 2; ++i) {
            const int row = rp * 2 + i;
            const int4 m = mq_buf[buf][i];
            float e0, e1, e2, e3;
            unpack2(sac[i][0], e0, e1);
            unpack2(sac[i][1], e2, e3);
            float4 e;
            e.x = m.x ? ex2(e0) : 0.f;
            e.y = m.y ? ex2(e1) : 0.f;
            e.z = m.z ? ex2(e2) : 0.f;
            e.w = m.w ? ex2(e3) : 0.f;
            rs[i] += (e.x + e.y) + (e.z + e.w);
            *(float4*)(attnbase + (size_t)row * kL + j0 + cg * 4) = e;
            uint4 u;
            u.x = f2tf32(e.x); u.y = f2tf32(e.y);
            u.z = f2tf32(e.z); u.w = f2tf32(e.w);
            *(uint4*)&S.p[buf][row][cg * 4] = u;
        }

        // ---- mask prefetch 2 tiles ahead ----
        {
            const int jm = (jt + 2 < NTILES) ? (jt + 2) * KT : 0;
            #pragma unroll
            for (int i = 0; i < 2; ++i)
                mq_buf[buf][i] =
                    *(const int4*)(mbase + (size_t)(rp * 2 + i) * kL + jm + cg * 4);
        }

        // ---- stage next a2 tile ----
        if (t < 64)
            *(float4*)&S.a2t[buf ^ 1][ar][ac * 4] = a2n;

        cp_wait1();        // v tile jt resident (only jt+1 pending)
        __syncthreads();   // publish p[buf]/a2t[buf^1]/v(jt)

        sprev = (sprev == 2) ? 0 : sprev + 1;
        snxt  = (snxt  == 2) ? 0 : snxt  + 1;
    }

    // ---- drain: MMA(63): p[1], v slot 63%3 = 0 ----
    {
        const uint32_t* vt = &S.v[sprev][0][0];
        const uint32_t ab = paddr[1];
        #pragma unroll
        for (int s = 0; s < 4; ++s) {
            uint32_t a[2][4];
            ldmatrix_x4(a[0], ab + (uint32_t)(s * 32));
            ldmatrix_x4(a[1], ab + (uint32_t)(16 * PSTRIDE * 4 + s * 32));
            #pragma unroll
            for (int nt = 0; nt < 4; ++nt) {
                const int n = 32 * wn + 8 * nt + qid;
                uint32_t b0 = vt[(size_t)(8 * s + tig) * VSTRIDE + n];
                uint32_t b1 = vt[(size_t)(8 * s + 4 + tig) * VSTRIDE + n];
                mma_tf32(acc[0][nt], a[0], b0, b1);
                mma_tf32(acc[1][nt], a[1], b0, b1);
            }
        }
    }

    // ---- rowsum reduce over 8 cg lanes (warp-local) ----
    float invr[2];
    #pragma unroll
    for (int i = 0; i < 2; ++i) {
        float r = rs[i];
        r += __shfl_xor_sync(0xffffffffu, r, 1);
        r += __shfl_xor_sync(0xffffffffu, r, 2);
        r += __shfl_xor_sync(0xffffffffu, r, 4);
        invr[i] = 1.0f / r;
        if (cg == 0) S.inv[rp * 2 + i] = invr[i];
    }
    __syncthreads();

    // ---- out epilogue: scale accumulators by row inv ----
    #pragma unroll
    for (int mt = 0; mt < 2; ++mt) {
        const int row0 = 32 * wm + 16 * mt + qid;
        const float ivlo = S.inv[row0];
        const float ivhi = S.inv[row0 + 8];
        #pragma unroll
        for (int nt = 0; nt < 4; ++nt) {
            const int col = 32 * wn + 8 * nt + 2 * tig;
            float2 lo; lo.x = acc[mt][nt][0] * ivlo; lo.y = acc[mt][nt][1] * ivlo;
            float2 hi; hi.x = acc[mt][nt][2] * ivhi; hi.y = acc[mt][nt][3] * ivhi;
            *(float2*)(outbase + (size_t)row0 * kDV + col)       = lo;
            *(float2*)(outbase + (size_t)(row0 + 8) * kDV + col) = hi;
        }
    }

    // ---- attn rescale: each thread rescales exactly the float4s it wrote ----
    #pragma unroll
    for (int i = 0; i < 2; ++i) {
        float* aprow = attnbase + (size_t)(rp * 2 + i) * kL + cg * 4;
        const float iv = invr[i];
        #pragma unroll 8
        for (int jt = 0; jt < NTILES; ++jt) {
            float4 e = *(const float4*)(aprow + jt * KT);
            e.x *= iv; e.y *= iv; e.z *= iv; e.w *= iv;
            *(float4*)(aprow + jt * KT) = e;
        }
    }
}

} // namespace

extern "C" void kernel_launch(void* const* d_in, const int* in_sizes, int n_in,
                              void* d_out, int out_size) {
    const float* v    = (const float*)d_in[0];
    const float* a1   = (const float*)d_in[1];
    const float* a2   = (const float*)d_in[2];
    const int*   mask = (const int*)d_in[3];

    float* out  = (float*)d_out;
    float* attn = out + (size_t)kB * kH * kL * kDV;

    const int smem = (int)sizeof(SmemLayout);
    cudaFuncSetAttribute(fra_kernel, cudaFuncAttributeMaxDynamicSharedMemorySize, smem);

    dim3 grid(kH, kL / TM, kB);   // heads fastest -> mask tile L2 reuse across 8 heads
    fra_kernel<<<grid, NT, smem>>>(v, a1, a2, mask, out, attn);
}